// round 5
// baseline (speedup 1.0000x reference)
#include <cuda_runtime.h>
#include <math.h>

#define NB   2
#define NO   512
#define NQ   512
#define NL   256
#define NH   8
#define ND   32
#define NHD  256
#define NOUT 128

// ---------------- scratch (device globals; no allocation allowed) ----------------
__device__ float g_aq[NB * NQ * NL];          // A_q + kb1
__device__ float g_ao[NB * NO * NL];          // A_o
__device__ float g_h1[NB * NO * NL];          // relu(h_obs@fw1+fb1)
__device__ float g_v [NB * NO * NHD];         // value features [b][o][h*32+d]
__device__ float g_logits[NB * NH * NQ * NO]; // [b][h][q][o]
__device__ float g_hq [NB * NQ * NHD];        // v_mean  [b][q][h*32+d]
__device__ float g_var[NB * NQ * NHD];        // variance [b][q][h*32+d]

// ---------------- position projections ----------------
// A_q[row,c] = kb1[c] + sum_i pos_q[i]*(kw1[i][c]+kw1[6+i][c])
// A_o[row,c] =          sum_i pos_o[i]*(kw1[3+i][c]-kw1[6+i][c])
__global__ void __launch_bounds__(NL) k_posproj(const float* __restrict__ pos_obs,
                                                const float* __restrict__ pos_query,
                                                const float* __restrict__ kw1,
                                                const float* __restrict__ kb1) {
    int row = blockIdx.x;
    int c   = threadIdx.x;
    if (row < NB * NQ) {
        const float* p = pos_query + row * 3;
        float acc = kb1[c];
#pragma unroll
        for (int i = 0; i < 3; i++)
            acc = fmaf(p[i], kw1[i * NL + c] + kw1[(6 + i) * NL + c], acc);
        g_aq[row * NL + c] = acc;
    } else {
        int r = row - NB * NQ;
        const float* p = pos_obs + r * 3;
        float acc = 0.f;
#pragma unroll
        for (int i = 0; i < 3; i++)
            acc = fmaf(p[i], kw1[(3 + i) * NL + c] - kw1[(6 + i) * NL + c], acc);
        g_ao[r * NL + c] = acc;
    }
}

// ---------------- generic MLP GEMM: C[M,N] = epi(A[M,256] @ W[256,N] + bias) ----------------
// EPI: 0 = none, 1 = relu, 2 = softplus
template <int N, int ROWS, int EPI>
__global__ void __launch_bounds__(N) k_gemm(const float* __restrict__ A,
                                            const float* __restrict__ W,
                                            const float* __restrict__ bias,
                                            float* __restrict__ C) {
    __shared__ __align__(16) float a_s[ROWS][NL];
    const int tid  = threadIdx.x;
    const int row0 = blockIdx.x * ROWS;
    for (int idx = tid; idx < ROWS * NL; idx += N)
        a_s[idx >> 8][idx & 255] = A[(row0 + (idx >> 8)) * NL + (idx & 255)];
    __syncthreads();

    float acc[ROWS];
#pragma unroll
    for (int r = 0; r < ROWS; r++) acc[r] = 0.f;

    for (int k4 = 0; k4 < NL; k4 += 4) {
        float w0 = W[(k4 + 0) * N + tid];
        float w1 = W[(k4 + 1) * N + tid];
        float w2 = W[(k4 + 2) * N + tid];
        float w3 = W[(k4 + 3) * N + tid];
#pragma unroll
        for (int r = 0; r < ROWS; r++) {
            float4 a = *reinterpret_cast<const float4*>(&a_s[r][k4]);
            acc[r] = fmaf(a.x, w0, acc[r]);
            acc[r] = fmaf(a.y, w1, acc[r]);
            acc[r] = fmaf(a.z, w2, acc[r]);
            acc[r] = fmaf(a.w, w3, acc[r]);
        }
    }
    float bb = bias[tid];
#pragma unroll
    for (int r = 0; r < ROWS; r++) {
        float v = acc[r] + bb;
        if (EPI == 1) v = fmaxf(v, 0.f);
        if (EPI == 2) v = fmaxf(v, 0.f) + log1pf(expf(-fabsf(v)));
        C[(row0 + r) * N + tid] = v;
    }
}

// ---------------- logits: delta MLP + RBF, fused ----------------
// One thread per (q,o) pair in a 16x16 tile. hidden_k = relu(aq_k + ao_k),
// delta[h] += hidden_k * kw2[k][h].
__global__ void __launch_bounds__(256) k_logits(const float* __restrict__ pos_obs,
                                                const float* __restrict__ pos_query,
                                                const float* __restrict__ kw2,
                                                const float* __restrict__ kb2,
                                                const float* __restrict__ log_sigma) {
    __shared__ __align__(16) float kw2_s[NL * NH];   // 8 KB
    __shared__ float aq_s[NL * 17];                  // [k][ql], pitch 17 (17 KB)
    __shared__ float ao_s[NL * 17];                  // [k][ol], pitch 17 (17 KB)
    __shared__ float pq_s[16][3], po_s[16][3];
    __shared__ float inv_s2[NH], kb2_s[NH];

    const int tid = threadIdx.x;
    const int o0  = blockIdx.x * 16;
    const int q0  = blockIdx.y * 16;
    const int b   = blockIdx.z;

    for (int idx = tid; idx < NL * NH; idx += 256) kw2_s[idx] = kw2[idx];
    for (int idx = tid; idx < 16 * NL; idx += 256) {
        int r = idx >> 8, k = idx & 255;
        aq_s[k * 17 + r] = g_aq[(b * NQ + q0 + r) * NL + k];
        ao_s[k * 17 + r] = g_ao[(b * NO + o0 + r) * NL + k];
    }
    if (tid < 48) {
        pq_s[tid / 3][tid % 3] = pos_query[(b * NQ + q0) * 3 + tid];
    } else if (tid < 96) {
        int t = tid - 48;
        po_s[t / 3][t % 3] = pos_obs[(b * NO + o0) * 3 + t];
    } else if (tid < 104) {
        int h = tid - 96;
        float s   = expf(log_sigma[h]);
        inv_s2[h] = 1.f / (s * s + 1e-6f);
        kb2_s[h]  = kb2[h];
    }
    __syncthreads();

    const int ol = tid & 15, ql = tid >> 4;
    float acc[8];
#pragma unroll
    for (int h = 0; h < 8; h++) acc[h] = 0.f;

#pragma unroll 4
    for (int k = 0; k < NL; k++) {
        float a   = aq_s[k * 17 + ql];   // broadcast within warp (2 distinct)
        float oo  = ao_s[k * 17 + ol];   // 16 consecutive words, conflict-free
        float hkv = fmaxf(a + oo, 0.f);
        const float4* wp = reinterpret_cast<const float4*>(kw2_s + k * 8);
        float4 w0 = wp[0], w1 = wp[1];   // broadcast (same address all lanes)
        acc[0] = fmaf(hkv, w0.x, acc[0]);
        acc[1] = fmaf(hkv, w0.y, acc[1]);
        acc[2] = fmaf(hkv, w0.z, acc[2]);
        acc[3] = fmaf(hkv, w0.w, acc[3]);
        acc[4] = fmaf(hkv, w1.x, acc[4]);
        acc[5] = fmaf(hkv, w1.y, acc[5]);
        acc[6] = fmaf(hkv, w1.z, acc[6]);
        acc[7] = fmaf(hkv, w1.w, acc[7]);
    }

    float dx = pq_s[ql][0] - po_s[ol][0];
    float dy = pq_s[ql][1] - po_s[ol][1];
    float dz = pq_s[ql][2] - po_s[ol][2];
    float dist2 = dx * dx + dy * dy + dz * dz;

    const int q = q0 + ql, o = o0 + ol;
    float* outp = g_logits + ((size_t)(b * NH) * NQ + q) * NO + o;
#pragma unroll
    for (int h = 0; h < NH; h++) {
        float t  = -dist2 * inv_s2[h];
        float lg = logf(expf(t) + 1e-8f) + acc[h] + kb2_s[h];
        outp[(size_t)h * NQ * NO] = lg;
    }
}

// ---------------- softmax + weighted mean/var ----------------
// One CTA per (b,h,q-tile of 16). Phase 1: row softmax into smem.
// Phase 2: mean = W@v, E2 = W@v^2, var = E2 - mean^2 (sum w == 1).
__global__ void __launch_bounds__(256) k_attn() {
    __shared__ float w_s[16][NO];    // 32 KB
    const int bid = blockIdx.x;
    const int qt = bid & 31, h = (bid >> 5) & 7, b = bid >> 8;
    const int q0 = qt * 16;
    const int tid = threadIdx.x, lane = tid & 31, warp = tid >> 5;

    const float* lbase = g_logits + (size_t)(b * NH + h) * NQ * NO;
    for (int r = warp; r < 16; r += 8) {
        const float* lp = lbase + (size_t)(q0 + r) * NO;
        float vals[16];
        float mx = -3.0e38f;
#pragma unroll
        for (int j = 0; j < 16; j++) {
            vals[j] = lp[lane + j * 32];
            mx = fmaxf(mx, vals[j]);
        }
#pragma unroll
        for (int s = 16; s > 0; s >>= 1) mx = fmaxf(mx, __shfl_xor_sync(0xffffffffu, mx, s));
        float sum = 0.f;
#pragma unroll
        for (int j = 0; j < 16; j++) { vals[j] = expf(vals[j] - mx); sum += vals[j]; }
#pragma unroll
        for (int s = 16; s > 0; s >>= 1) sum += __shfl_xor_sync(0xffffffffu, sum, s);
        float inv = 1.f / sum;
#pragma unroll
        for (int j = 0; j < 16; j++) w_s[r][lane + j * 32] = vals[j] * inv;
    }
    __syncthreads();

    const int d = tid & 31, qq = tid >> 5;  // qq in 0..7, handles rows qq and qq+8
    const float* vp = g_v + (size_t)(b * NO) * NHD + h * ND + d;
    float m1 = 0.f, e1 = 0.f, m2 = 0.f, e2 = 0.f;
#pragma unroll 4
    for (int o = 0; o < NO; o++) {
        float v  = __ldg(vp + (size_t)o * NHD);  // 128B/warp, L1-resident across warps
        float v2 = v * v;
        float wa = w_s[qq][o];       // broadcast
        float wb = w_s[qq + 8][o];   // broadcast
        m1 = fmaf(wa, v, m1);  e1 = fmaf(wa, v2, e1);
        m2 = fmaf(wb, v, m2);  e2 = fmaf(wb, v2, e2);
    }
    size_t base = (size_t)(b * NQ + q0) * NHD + h * ND + d;
    g_hq [base + (size_t)qq * NHD]       = m1;
    g_var[base + (size_t)qq * NHD]       = e1 - m1 * m1;
    g_hq [base + (size_t)(qq + 8) * NHD] = m2;
    g_var[base + (size_t)(qq + 8) * NHD] = e2 - m2 * m2;
}

// ---------------- launcher ----------------
extern "C" void kernel_launch(void* const* d_in, const int* in_sizes, int n_in,
                              void* d_out, int out_size) {
    const float* h_obs     = (const float*)d_in[0];
    const float* pos_obs   = (const float*)d_in[1];
    const float* pos_query = (const float*)d_in[2];
    const float* fw1       = (const float*)d_in[3];
    const float* fb1       = (const float*)d_in[4];
    const float* fw2       = (const float*)d_in[5];
    const float* fb2       = (const float*)d_in[6];
    const float* log_sigma = (const float*)d_in[7];
    const float* kw1       = (const float*)d_in[8];
    const float* kb1       = (const float*)d_in[9];
    const float* kw2       = (const float*)d_in[10];
    const float* kb2       = (const float*)d_in[11];
    const float* ow        = (const float*)d_in[12];
    const float* ob        = (const float*)d_in[13];
    const float* vw        = (const float*)d_in[14];
    const float* vb        = (const float*)d_in[15];
    float* out = (float*)d_out;

    float *p_h1, *p_v, *p_hq, *p_var;
    cudaGetSymbolAddress((void**)&p_h1,  g_h1);
    cudaGetSymbolAddress((void**)&p_v,   g_v);
    cudaGetSymbolAddress((void**)&p_hq,  g_hq);
    cudaGetSymbolAddress((void**)&p_var, g_var);

    // position projections for the factored key-MLP
    k_posproj<<<NB * (NQ + NO), NL>>>(pos_obs, pos_query, kw1, kb1);

    // value MLP: v = relu(h_obs@fw1+fb1)@fw2+fb2
    k_gemm<256, 8, 1><<<NB * NO / 8, 256>>>(h_obs, fw1, fb1, p_h1);
    k_gemm<256, 8, 0><<<NB * NO / 8, 256>>>(p_h1, fw2, fb2, p_v);

    // logits = log(rbf+1e-8) + delta
    dim3 glog(NO / 16, NQ / 16, NB);
    k_logits<<<glog, 256>>>(pos_obs, pos_query, kw2, kb2, log_sigma);

    // softmax + weighted mean / variance
    k_attn<<<NB * NH * (NQ / 16), 256>>>();

    // outputs: mean = hq@ow+ob ; var_out = softplus(var@vw+vb)
    k_gemm<128, 8, 0><<<NB * NQ / 8, 128>>>(p_hq, ow, ob, out);
    k_gemm<128, 8, 2><<<NB * NQ / 8, 128>>>(p_var, vw, vb, out + NB * NQ * NOUT);
}

// round 6
// speedup vs baseline: 1.0185x; 1.0185x over previous
#include <cuda_runtime.h>
#include <math.h>

#define NB   2
#define NO   512
#define NQ   512
#define NL   256
#define NH   8
#define ND   32
#define NHD  256
#define NOUT 128

// ---------------- scratch (device globals; no allocation allowed) ----------------
__device__ float g_aq[NB * NQ * NL];          // A_q + kb1
__device__ float g_ao[NB * NO * NL];          // A_o
__device__ float g_h1[NB * NO * NL];          // relu(h_obs@fw1+fb1)
__device__ float g_v [NB * NO * NHD];         // value features [b][o][h*32+d]
__device__ float g_logits[NB * NH * NQ * NO]; // [b][h][q][o]
__device__ float g_hq [NB * NQ * NHD];        // v_mean  [b][q][h*32+d]
__device__ float g_var[NB * NQ * NHD];        // variance [b][q][h*32+d]

// ---------------- position projections ----------------
// A_q[row,c] = kb1[c] + sum_i pos_q[i]*(kw1[i][c]+kw1[6+i][c])
// A_o[row,c] =          sum_i pos_o[i]*(kw1[3+i][c]-kw1[6+i][c])
__global__ void __launch_bounds__(NL) k_posproj(const float* __restrict__ pos_obs,
                                                const float* __restrict__ pos_query,
                                                const float* __restrict__ kw1,
                                                const float* __restrict__ kb1) {
    int row = blockIdx.x;
    int c   = threadIdx.x;
    if (row < NB * NQ) {
        const float* p = pos_query + row * 3;
        float acc = kb1[c];
#pragma unroll
        for (int i = 0; i < 3; i++)
            acc = fmaf(p[i], kw1[i * NL + c] + kw1[(6 + i) * NL + c], acc);
        g_aq[row * NL + c] = acc;
    } else {
        int r = row - NB * NQ;
        const float* p = pos_obs + r * 3;
        float acc = 0.f;
#pragma unroll
        for (int i = 0; i < 3; i++)
            acc = fmaf(p[i], kw1[(3 + i) * NL + c] - kw1[(6 + i) * NL + c], acc);
        g_ao[r * NL + c] = acc;
    }
}

// ---------------- generic MLP GEMM: C[M,N] = epi(A[M,256] @ W[256,N] + bias) ----------------
// EPI: 0 = none, 1 = relu, 2 = softplus
template <int N, int ROWS, int EPI>
__global__ void __launch_bounds__(N) k_gemm(const float* __restrict__ A,
                                            const float* __restrict__ W,
                                            const float* __restrict__ bias,
                                            float* __restrict__ C) {
    __shared__ __align__(16) float a_s[ROWS][NL];
    const int tid  = threadIdx.x;
    const int row0 = blockIdx.x * ROWS;
    for (int idx = tid; idx < ROWS * NL; idx += N)
        a_s[idx >> 8][idx & 255] = A[(row0 + (idx >> 8)) * NL + (idx & 255)];
    __syncthreads();

    float acc[ROWS];
#pragma unroll
    for (int r = 0; r < ROWS; r++) acc[r] = 0.f;

    for (int k4 = 0; k4 < NL; k4 += 4) {
        float w0 = W[(k4 + 0) * N + tid];
        float w1 = W[(k4 + 1) * N + tid];
        float w2 = W[(k4 + 2) * N + tid];
        float w3 = W[(k4 + 3) * N + tid];
#pragma unroll
        for (int r = 0; r < ROWS; r++) {
            float4 a = *reinterpret_cast<const float4*>(&a_s[r][k4]);
            acc[r] = fmaf(a.x, w0, acc[r]);
            acc[r] = fmaf(a.y, w1, acc[r]);
            acc[r] = fmaf(a.z, w2, acc[r]);
            acc[r] = fmaf(a.w, w3, acc[r]);
        }
    }
    float bb = bias[tid];
#pragma unroll
    for (int r = 0; r < ROWS; r++) {
        float v = acc[r] + bb;
        if (EPI == 1) v = fmaxf(v, 0.f);
        if (EPI == 2) v = fmaxf(v, 0.f) + log1pf(expf(-fabsf(v)));
        C[(row0 + r) * N + tid] = v;
    }
}

// ---------------- logits: delta MLP + RBF, fused ----------------
// One thread per (q,o) pair in a 16x16 tile. hidden_k = relu(aq_k + ao_k),
// delta[h] += hidden_k * kw2[k][h].
__global__ void __launch_bounds__(256) k_logits(const float* __restrict__ pos_obs,
                                                const float* __restrict__ pos_query,
                                                const float* __restrict__ kw2,
                                                const float* __restrict__ kb2,
                                                const float* __restrict__ log_sigma) {
    __shared__ __align__(16) float kw2_s[NL * NH];   // 8 KB
    __shared__ float aq_s[NL * 17];                  // [k][ql], pitch 17 (17 KB)
    __shared__ float ao_s[NL * 17];                  // [k][ol], pitch 17 (17 KB)
    __shared__ float pq_s[16][3], po_s[16][3];
    __shared__ float inv_s2[NH], kb2_s[NH];

    const int tid = threadIdx.x;
    const int o0  = blockIdx.x * 16;
    const int q0  = blockIdx.y * 16;
    const int b   = blockIdx.z;

    for (int idx = tid; idx < NL * NH; idx += 256) kw2_s[idx] = kw2[idx];
    for (int idx = tid; idx < 16 * NL; idx += 256) {
        int r = idx >> 8, k = idx & 255;
        aq_s[k * 17 + r] = g_aq[(b * NQ + q0 + r) * NL + k];
        ao_s[k * 17 + r] = g_ao[(b * NO + o0 + r) * NL + k];
    }
    if (tid < 48) {
        pq_s[tid / 3][tid % 3] = pos_query[(b * NQ + q0) * 3 + tid];
    } else if (tid < 96) {
        int t = tid - 48;
        po_s[t / 3][t % 3] = pos_obs[(b * NO + o0) * 3 + t];
    } else if (tid < 104) {
        int h = tid - 96;
        float s   = expf(log_sigma[h]);
        inv_s2[h] = 1.f / (s * s + 1e-6f);
        kb2_s[h]  = kb2[h];
    }
    __syncthreads();

    const int ol = tid & 15, ql = tid >> 4;
    float acc[8];
#pragma unroll
    for (int h = 0; h < 8; h++) acc[h] = 0.f;

#pragma unroll 4
    for (int k = 0; k < NL; k++) {
        float a   = aq_s[k * 17 + ql];   // broadcast within warp (2 distinct)
        float oo  = ao_s[k * 17 + ol];   // 16 consecutive words, conflict-free
        float hkv = fmaxf(a + oo, 0.f);
        const float4* wp = reinterpret_cast<const float4*>(kw2_s + k * 8);
        float4 w0 = wp[0], w1 = wp[1];   // broadcast (same address all lanes)
        acc[0] = fmaf(hkv, w0.x, acc[0]);
        acc[1] = fmaf(hkv, w0.y, acc[1]);
        acc[2] = fmaf(hkv, w0.z, acc[2]);
        acc[3] = fmaf(hkv, w0.w, acc[3]);
        acc[4] = fmaf(hkv, w1.x, acc[4]);
        acc[5] = fmaf(hkv, w1.y, acc[5]);
        acc[6] = fmaf(hkv, w1.z, acc[6]);
        acc[7] = fmaf(hkv, w1.w, acc[7]);
    }

    float dx = pq_s[ql][0] - po_s[ol][0];
    float dy = pq_s[ql][1] - po_s[ol][1];
    float dz = pq_s[ql][2] - po_s[ol][2];
    float dist2 = dx * dx + dy * dy + dz * dz;

    const int q = q0 + ql, o = o0 + ol;
    float* outp = g_logits + ((size_t)(b * NH) * NQ + q) * NO + o;
#pragma unroll
    for (int h = 0; h < NH; h++) {
        float t  = -dist2 * inv_s2[h];
        float lg = logf(expf(t) + 1e-8f) + acc[h] + kb2_s[h];
        outp[(size_t)h * NQ * NO] = lg;
    }
}

// ---------------- softmax + weighted mean/var ----------------
// One CTA per (b,h,q-tile of 16). Phase 1: row softmax into smem.
// Phase 2: mean = W@v, E2 = W@v^2, var = E2 - mean^2 (sum w == 1).
__global__ void __launch_bounds__(256) k_attn() {
    __shared__ float w_s[16][NO];    // 32 KB
    const int bid = blockIdx.x;
    const int qt = bid & 31, h = (bid >> 5) & 7, b = bid >> 8;
    const int q0 = qt * 16;
    const int tid = threadIdx.x, lane = tid & 31, warp = tid >> 5;

    const float* lbase = g_logits + (size_t)(b * NH + h) * NQ * NO;
    for (int r = warp; r < 16; r += 8) {
        const float* lp = lbase + (size_t)(q0 + r) * NO;
        float vals[16];
        float mx = -3.0e38f;
#pragma unroll
        for (int j = 0; j < 16; j++) {
            vals[j] = lp[lane + j * 32];
            mx = fmaxf(mx, vals[j]);
        }
#pragma unroll
        for (int s = 16; s > 0; s >>= 1) mx = fmaxf(mx, __shfl_xor_sync(0xffffffffu, mx, s));
        float sum = 0.f;
#pragma unroll
        for (int j = 0; j < 16; j++) { vals[j] = expf(vals[j] - mx); sum += vals[j]; }
#pragma unroll
        for (int s = 16; s > 0; s >>= 1) sum += __shfl_xor_sync(0xffffffffu, sum, s);
        float inv = 1.f / sum;
#pragma unroll
        for (int j = 0; j < 16; j++) w_s[r][lane + j * 32] = vals[j] * inv;
    }
    __syncthreads();

    const int d = tid & 31, qq = tid >> 5;  // qq in 0..7, handles rows qq and qq+8
    const float* vp = g_v + (size_t)(b * NO) * NHD + h * ND + d;
    float m1 = 0.f, e1 = 0.f, m2 = 0.f, e2 = 0.f;
#pragma unroll 4
    for (int o = 0; o < NO; o++) {
        float v  = __ldg(vp + (size_t)o * NHD);  // 128B/warp, L1-resident across warps
        float v2 = v * v;
        float wa = w_s[qq][o];       // broadcast
        float wb = w_s[qq + 8][o];   // broadcast
        m1 = fmaf(wa, v, m1);  e1 = fmaf(wa, v2, e1);
        m2 = fmaf(wb, v, m2);  e2 = fmaf(wb, v2, e2);
    }
    size_t base = (size_t)(b * NQ + q0) * NHD + h * ND + d;
    g_hq [base + (size_t)qq * NHD]       = m1;
    g_var[base + (size_t)qq * NHD]       = e1 - m1 * m1;
    g_hq [base + (size_t)(qq + 8) * NHD] = m2;
    g_var[base + (size_t)(qq + 8) * NHD] = e2 - m2 * m2;
}

// ---------------- launcher ----------------
extern "C" void kernel_launch(void* const* d_in, const int* in_sizes, int n_in,
                              void* d_out, int out_size) {
    const float* h_obs     = (const float*)d_in[0];
    const float* pos_obs   = (const float*)d_in[1];
    const float* pos_query = (const float*)d_in[2];
    const float* fw1       = (const float*)d_in[3];
    const float* fb1       = (const float*)d_in[4];
    const float* fw2       = (const float*)d_in[5];
    const float* fb2       = (const float*)d_in[6];
    const float* log_sigma = (const float*)d_in[7];
    const float* kw1       = (const float*)d_in[8];
    const float* kb1       = (const float*)d_in[9];
    const float* kw2       = (const float*)d_in[10];
    const float* kb2       = (const float*)d_in[11];
    const float* ow        = (const float*)d_in[12];
    const float* ob        = (const float*)d_in[13];
    const float* vw        = (const float*)d_in[14];
    const float* vb        = (const float*)d_in[15];
    float* out = (float*)d_out;

    float *p_h1, *p_v, *p_hq, *p_var;
    cudaGetSymbolAddress((void**)&p_h1,  g_h1);
    cudaGetSymbolAddress((void**)&p_v,   g_v);
    cudaGetSymbolAddress((void**)&p_hq,  g_hq);
    cudaGetSymbolAddress((void**)&p_var, g_var);

    // position projections for the factored key-MLP
    k_posproj<<<NB * (NQ + NO), NL>>>(pos_obs, pos_query, kw1, kb1);

    // value MLP: v = relu(h_obs@fw1+fb1)@fw2+fb2
    k_gemm<256, 8, 1><<<NB * NO / 8, 256>>>(h_obs, fw1, fb1, p_h1);
    k_gemm<256, 8, 0><<<NB * NO / 8, 256>>>(p_h1, fw2, fb2, p_v);

    // logits = log(rbf+1e-8) + delta
    dim3 glog(NO / 16, NQ / 16, NB);
    k_logits<<<glog, 256>>>(pos_obs, pos_query, kw2, kb2, log_sigma);

    // softmax + weighted mean / variance
    k_attn<<<NB * NH * (NQ / 16), 256>>>();

    // outputs: mean = hq@ow+ob ; var_out = softplus(var@vw+vb)
    k_gemm<128, 8, 0><<<NB * NQ / 8, 128>>>(p_hq, ow, ob, out);
    k_gemm<128, 8, 2><<<NB * NQ / 8, 128>>>(p_var, vw, vb, out + NB * NQ * NOUT);
}